// round 1
// baseline (speedup 1.0000x reference)
#include <cuda_runtime.h>
#include <math.h>

#define EMBED   1024
#define HEADS   16
#define HD      64
#define NB      12
#define SEQ     257
#define BATCH   32
#define MROWS   (BATCH*SEQ)      // 8224
#define HIDDEN  2816

// ---------------- scratch (device globals; no allocations allowed) ----------
__device__ float g_a[MROWS*EMBED];        // normalized activations (33.7 MB)
__device__ float g_qkv[MROWS*3*EMBED];    // qkv / reused as w3-output (101 MB)
__device__ float g_o[MROWS*EMBED];        // attention output / cond temp
__device__ float g_u[MROWS*HIDDEN];       // w1 output -> fused silu*gate
__device__ float g_fc[SEQ*32*2];          // rope cos/sin table

// ---------------- reductions ------------------------------------------------
__device__ __forceinline__ float block_sum(float v, float* red) {
    int tid = threadIdx.x;
    #pragma unroll
    for (int o = 16; o > 0; o >>= 1) v += __shfl_xor_sync(0xffffffffu, v, o);
    if ((tid & 31) == 0) red[tid >> 5] = v;
    __syncthreads();
    if (tid == 0) {
        float s = red[0];
        int nw = blockDim.x >> 5;
        for (int i = 1; i < nw; i++) s += red[i];
        red[0] = s;
    }
    __syncthreads();
    float r = red[0];
    __syncthreads();
    return r;
}

__device__ __forceinline__ float block_max(float v, float* red) {
    int tid = threadIdx.x;
    #pragma unroll
    for (int o = 16; o > 0; o >>= 1) v = fmaxf(v, __shfl_xor_sync(0xffffffffu, v, o));
    if ((tid & 31) == 0) red[tid >> 5] = v;
    __syncthreads();
    if (tid == 0) {
        float s = red[0];
        int nw = blockDim.x >> 5;
        for (int i = 1; i < nw; i++) s = fmaxf(s, red[i]);
        red[0] = s;
    }
    __syncthreads();
    float r = red[0];
    __syncthreads();
    return r;
}

// ---------------- SGEMM: C[M,N] = A[M,K] @ B[K,N] (+bias[N]) (+res[M,N]) ----
// 128x128 block tile, BK=8, 256 threads, 8x8 microtile.
__global__ __launch_bounds__(256) void ar_sgemm(
    const float* __restrict__ A, const float* __restrict__ B,
    const float* __restrict__ bias, const float* __restrict__ res,
    float* __restrict__ C, int M, int N, int K)
{
    __shared__ float As[8][128];
    __shared__ float Bs[8][128];
    int tid = threadIdx.x;
    int bm = blockIdx.y * 128, bn = blockIdx.x * 128;
    int tx = tid & 15, ty = tid >> 4;
    int arow = tid >> 1, acol = (tid & 1) << 2;
    int brow = tid >> 5, bcol = (tid & 31) << 2;
    bool aval = (bm + arow) < M;
    const float* Aptr = A + (size_t)(bm + arow) * K + acol;
    const float* Bptr = B + (size_t)brow * N + bn + bcol;

    float acc[8][8];
    #pragma unroll
    for (int i = 0; i < 8; i++)
        #pragma unroll
        for (int j = 0; j < 8; j++) acc[i][j] = 0.f;

    for (int k0 = 0; k0 < K; k0 += 8) {
        float4 av = aval ? *(const float4*)Aptr : make_float4(0.f, 0.f, 0.f, 0.f);
        Aptr += 8;
        As[acol + 0][arow] = av.x;
        As[acol + 1][arow] = av.y;
        As[acol + 2][arow] = av.z;
        As[acol + 3][arow] = av.w;
        float4 bv = *(const float4*)Bptr;
        Bptr += (size_t)8 * N;
        *(float4*)&Bs[brow][bcol] = bv;
        __syncthreads();
        #pragma unroll
        for (int kk = 0; kk < 8; kk++) {
            float4 a0 = *(float4*)&As[kk][ty * 8];
            float4 a1 = *(float4*)&As[kk][ty * 8 + 4];
            float4 b0 = *(float4*)&Bs[kk][tx * 8];
            float4 b1 = *(float4*)&Bs[kk][tx * 8 + 4];
            float ra[8] = {a0.x, a0.y, a0.z, a0.w, a1.x, a1.y, a1.z, a1.w};
            float rb[8] = {b0.x, b0.y, b0.z, b0.w, b1.x, b1.y, b1.z, b1.w};
            #pragma unroll
            for (int i = 0; i < 8; i++)
                #pragma unroll
                for (int j = 0; j < 8; j++)
                    acc[i][j] = fmaf(ra[i], rb[j], acc[i][j]);
        }
        __syncthreads();
    }

    #pragma unroll
    for (int i = 0; i < 8; i++) {
        int gm = bm + ty * 8 + i;
        if (gm >= M) continue;
        #pragma unroll
        for (int j = 0; j < 8; j += 4) {
            int gn = bn + tx * 8 + j;
            float4 v = make_float4(acc[i][j], acc[i][j+1], acc[i][j+2], acc[i][j+3]);
            if (bias) {
                v.x += bias[gn]; v.y += bias[gn+1]; v.z += bias[gn+2]; v.w += bias[gn+3];
            }
            if (res) {
                float4 r = *(const float4*)(res + (size_t)gm * N + gn);
                v.x += r.x; v.y += r.y; v.z += r.z; v.w += r.w;
            }
            *(float4*)(C + (size_t)gm * N + gn) = v;
        }
    }
}

// ---------------- rope frequency table --------------------------------------
__global__ void ar_freqs(float* __restrict__ fc) {
    int t = blockIdx.x * blockDim.x + threadIdx.x;
    if (t >= SEQ * 32) return;
    int p = t >> 5, j = t & 31;
    float c = 0.f, s = 0.f;
    if (p > 0) {                       // cls token (p==0) keeps cos=sin=0 (ref!)
        int pp = p - 1, yy = pp >> 4, xx = pp & 15;
        int i = j & 15;
        float fr = powf(10000.0f, -(float)i * (1.0f / 16.0f));
        float tt = (j < 16) ? (float)yy : (float)xx;
        float ang = tt * fr;
        c = cosf(ang); s = sinf(ang);
    }
    fc[2 * t] = c;
    fc[2 * t + 1] = s;
}

// ---------------- assemble (cond | patch) + pos + LayerNorm ------------------
__global__ __launch_bounds__(256) void ar_assemble_ln(
    const float* __restrict__ patch, const float* __restrict__ condr,
    const float* __restrict__ pos, const float* __restrict__ g,
    const float* __restrict__ bta, float* __restrict__ h)
{
    __shared__ float buf[EMBED];
    __shared__ float red[8];
    int m = blockIdx.x, tid = threadIdx.x;
    int b = m / SEQ, s = m % SEQ;
    const float* src = (s == 0) ? (condr + (size_t)b * EMBED)
                                : (patch + ((size_t)(b * 256 + s - 1)) * EMBED);
    float lsum = 0.f;
    for (int d = tid; d < EMBED; d += 256) {
        float v = src[d] + pos[(size_t)s * EMBED + d];
        buf[d] = v; lsum += v;
    }
    float mean = block_sum(lsum, red) * (1.f / EMBED);
    float ls2 = 0.f;
    for (int d = tid; d < EMBED; d += 256) {
        float dv = buf[d] - mean; ls2 += dv * dv;
    }
    float var = block_sum(ls2, red) * (1.f / EMBED);
    float rinv = rsqrtf(var + 1e-6f);
    for (int d = tid; d < EMBED; d += 256)
        h[(size_t)m * EMBED + d] = (buf[d] - mean) * rinv * g[d] + bta[d];
}

// ---------------- RMSNorm ---------------------------------------------------
__global__ __launch_bounds__(256) void ar_rmsnorm(
    const float* __restrict__ x, const float* __restrict__ w, float* __restrict__ out)
{
    __shared__ float buf[EMBED];
    __shared__ float red[8];
    int m = blockIdx.x, tid = threadIdx.x;
    const float* xr = x + (size_t)m * EMBED;
    float ss = 0.f;
    for (int d = tid; d < EMBED; d += 256) {
        float v = xr[d]; buf[d] = v; ss += v * v;
    }
    ss = block_sum(ss, red);
    float r = rsqrtf(ss * (1.f / EMBED) + 1e-5f);
    for (int d = tid; d < EMBED; d += 256)
        out[(size_t)m * EMBED + d] = buf[d] * r * w[d];
}

// ---------------- rope (in-place on q and k halves of qkv) -------------------
__global__ void ar_rope(float* __restrict__ qkv, const float* __restrict__ fc) {
    int t = blockIdx.x * blockDim.x + threadIdx.x;
    if (t >= MROWS * 512) return;
    int m = t >> 9, r = t & 511;
    int hh = r >> 5, j = r & 31;
    int s = m % SEQ;
    float c  = fc[(s * 32 + j) * 2];
    float sn = fc[(s * 32 + j) * 2 + 1];
    float* q = qkv + (size_t)m * (3 * EMBED) + hh * HD + 2 * j;
    float x0 = q[0], x1 = q[1];
    q[0] = x0 * c - x1 * sn;
    q[1] = x1 * c + x0 * sn;
    float* k = q + EMBED;
    x0 = k[0]; x1 = k[1];
    k[0] = x0 * c - x1 * sn;
    k[1] = x1 * c + x0 * sn;
}

// ---------------- attention: rows 0..255, whole K/V in smem -----------------
__device__ __forceinline__ void ar_attn_row(
    int qrow, int b, int h, const float* __restrict__ qkv,
    const float* __restrict__ Ks, const float* __restrict__ Vs,
    float* __restrict__ o)
{
    const float4* qp = (const float4*)(qkv + ((size_t)(b * SEQ + qrow)) * (3 * EMBED) + h * HD);
    float4 qv[16];
    #pragma unroll
    for (int i = 0; i < 16; i++) qv[i] = qp[i];
    float acc[64];
    #pragma unroll
    for (int d = 0; d < 64; d++) acc[d] = 0.f;
    float mx = -1e30f, l = 0.f;
    for (int j = 0; j <= qrow; j++) {
        const float4* kr = (const float4*)(Ks + j * 64);
        float s0 = 0.f, s1 = 0.f, s2 = 0.f, s3 = 0.f;
        #pragma unroll
        for (int i = 0; i < 16; i++) {
            float4 kk = kr[i];
            s0 = fmaf(qv[i].x, kk.x, s0);
            s1 = fmaf(qv[i].y, kk.y, s1);
            s2 = fmaf(qv[i].z, kk.z, s2);
            s3 = fmaf(qv[i].w, kk.w, s3);
        }
        float s = ((s0 + s1) + (s2 + s3)) * 0.125f;
        float nm = fmaxf(mx, s);
        float corr = __expf(mx - nm);
        float p = __expf(s - nm);
        l = l * corr + p;
        const float4* vr = (const float4*)(Vs + j * 64);
        #pragma unroll
        for (int i = 0; i < 16; i++) {
            float4 vv = vr[i];
            acc[4*i+0] = fmaf(acc[4*i+0], corr, p * vv.x);
            acc[4*i+1] = fmaf(acc[4*i+1], corr, p * vv.y);
            acc[4*i+2] = fmaf(acc[4*i+2], corr, p * vv.z);
            acc[4*i+3] = fmaf(acc[4*i+3], corr, p * vv.w);
        }
        mx = nm;
    }
    float inv = 1.f / l;
    float* op = o + ((size_t)(b * SEQ + qrow)) * EMBED + h * HD;
    #pragma unroll
    for (int d = 0; d < 64; d++) op[d] = acc[d] * inv;
}

__global__ __launch_bounds__(128) void ar_attn(const float* __restrict__ qkv,
                                               float* __restrict__ o)
{
    extern __shared__ float sm[];
    float* Ks = sm;
    float* Vs = sm + SEQ * 64;
    int h = blockIdx.x, b = blockIdx.y, tid = threadIdx.x;
    const float* base = qkv + (size_t)b * SEQ * (3 * EMBED) + EMBED + h * HD;
    for (int idx = tid; idx < SEQ * 16; idx += 128) {
        int s = idx >> 4, c = idx & 15;
        *(float4*)(Ks + s * 64 + c * 4) = *(const float4*)(base + (size_t)s * (3 * EMBED) + c * 4);
        *(float4*)(Vs + s * 64 + c * 4) = *(const float4*)(base + EMBED + (size_t)s * (3 * EMBED) + c * 4);
    }
    __syncthreads();
    // triangle-balanced pairing: each thread gets rows t and 255-t -> 257 iters
    ar_attn_row(tid, b, h, qkv, Ks, Vs, o);
    ar_attn_row(255 - tid, b, h, qkv, Ks, Vs, o);
}

// ---------------- attention row 256 (longest row, j-parallel) ---------------
__global__ __launch_bounds__(256) void ar_attn_last(const float* __restrict__ qkv,
                                                    float* __restrict__ o)
{
    __shared__ float qs[64];
    __shared__ float sc[SEQ];
    __shared__ float red[8];
    __shared__ float part[4][64];
    int h = blockIdx.x, b = blockIdx.y, tid = threadIdx.x;
    const float* qrow = qkv + ((size_t)(b * SEQ + 256)) * (3 * EMBED) + h * HD;
    if (tid < 64) qs[tid] = qrow[tid];
    __syncthreads();
    const float* kbase = qkv + (size_t)b * SEQ * (3 * EMBED) + EMBED + (size_t)h * HD;
    float lm = -1e30f;
    for (int j = tid; j < SEQ; j += 256) {
        const float* kr = kbase + (size_t)j * (3 * EMBED);
        float s = 0.f;
        #pragma unroll
        for (int d = 0; d < 64; d++) s = fmaf(qs[d], kr[d], s);
        s *= 0.125f;
        sc[j] = s;
        lm = fmaxf(lm, s);
    }
    float M = block_max(lm, red);
    float ls = 0.f;
    for (int j = tid; j < SEQ; j += 256) {
        float p = __expf(sc[j] - M);
        sc[j] = p;
        ls += p;
    }
    float L = block_sum(ls, red);
    int d = tid & 63, c = tid >> 6;
    const float* vbase = kbase + EMBED;
    float a = 0.f;
    for (int j = c; j < SEQ; j += 4)
        a = fmaf(sc[j], vbase[(size_t)j * (3 * EMBED) + d], a);
    part[c][d] = a;
    __syncthreads();
    if (tid < 64) {
        float s = part[0][tid] + part[1][tid] + part[2][tid] + part[3][tid];
        o[((size_t)(b * SEQ + 256)) * EMBED + h * HD + tid] = s / L;
    }
}

// ---------------- fused silu(u) * v -----------------------------------------
__global__ void ar_silu_mul(float* __restrict__ u, const float* __restrict__ v, int n) {
    int i = blockIdx.x * blockDim.x + threadIdx.x;
    if (i < n) {
        float uu = u[i];
        float s = uu / (1.f + __expf(-uu));
        u[i] = s * v[i];
    }
}

// ---------------- host orchestration ----------------------------------------
static inline void launch_gemm(const float* A, const float* B, const float* bias,
                               const float* res, float* C, int M, int N, int K) {
    dim3 grid((N + 127) / 128, (M + 127) / 128);
    ar_sgemm<<<grid, 256>>>(A, B, bias, res, C, M, N, K);
}

extern "C" void kernel_launch(void* const* d_in, const int* in_sizes, int n_in,
                              void* d_out, int out_size)
{
    const float* x       = (const float*)d_in[0];
    const float* cond    = (const float*)d_in[1];
    const float* patch_w = (const float*)d_in[2];
    const float* patch_b = (const float*)d_in[3];
    const float* ln_g    = (const float*)d_in[4];
    const float* ln_b    = (const float*)d_in[5];
    const float* pos     = (const float*)d_in[6];
    const float* cond_w  = (const float*)d_in[7];
    const float* cond_b  = (const float*)d_in[8];
    const float* wqkv    = (const float*)d_in[9];
    const float* wo      = (const float*)d_in[10];
    const float* w1      = (const float*)d_in[11];
    const float* w2      = (const float*)d_in[12];
    const float* w3      = (const float*)d_in[13];
    const float* anw     = (const float*)d_in[14];
    const float* fnw     = (const float*)d_in[15];
    float* h = (float*)d_out;

    float *pa, *pqkv, *po, *pu, *pfc;
    cudaGetSymbolAddress((void**)&pa,   g_a);
    cudaGetSymbolAddress((void**)&pqkv, g_qkv);
    cudaGetSymbolAddress((void**)&po,   g_o);
    cudaGetSymbolAddress((void**)&pu,   g_u);
    cudaGetSymbolAddress((void**)&pfc,  g_fc);

    cudaFuncSetAttribute(ar_attn, cudaFuncAttributeMaxDynamicSharedMemorySize,
                         SEQ * 64 * 2 * (int)sizeof(float));

    // rope table
    ar_freqs<<<(SEQ * 32 + 255) / 256, 256>>>(pfc);
    // patch embed (8192 x 768 @ 768 x 1024) -> g_a ; cond embed -> g_o
    launch_gemm(x, patch_w, patch_b, nullptr, pa, BATCH * 256, EMBED, 768);
    launch_gemm(cond, cond_w, cond_b, nullptr, po, BATCH, EMBED, EMBED);
    // assemble + pos + layernorm -> h (d_out)
    ar_assemble_ln<<<MROWS, 256>>>(pa, po, pos, ln_g, ln_b, h);

    for (int l = 0; l < NB; l++) {
        const float* wqkv_l = wqkv + (size_t)l * EMBED * (3 * EMBED);
        const float* wo_l   = wo   + (size_t)l * EMBED * EMBED;
        const float* w1_l   = w1   + (size_t)l * EMBED * HIDDEN;
        const float* w2_l   = w2   + (size_t)l * HIDDEN * EMBED;
        const float* w3_l   = w3   + (size_t)l * EMBED * HIDDEN;

        ar_rmsnorm<<<MROWS, 256>>>(h, anw + (size_t)l * EMBED, pa);
        launch_gemm(pa, wqkv_l, nullptr, nullptr, pqkv, MROWS, 3 * EMBED, EMBED);
        ar_rope<<<(MROWS * 512 + 255) / 256, 256>>>(pqkv, pfc);
        ar_attn<<<dim3(HEADS, BATCH), 128, SEQ * 64 * 2 * (int)sizeof(float)>>>(pqkv, po);
        ar_attn_last<<<dim3(HEADS, BATCH), 256>>>(pqkv, po);
        launch_gemm(po, wo_l, nullptr, h, h, MROWS, EMBED, EMBED);

        ar_rmsnorm<<<MROWS, 256>>>(h, fnw + (size_t)l * EMBED, pa);
        launch_gemm(pa, w1_l, nullptr, nullptr, pu, MROWS, HIDDEN, EMBED);
        launch_gemm(pa, w3_l, nullptr, nullptr, pqkv, MROWS, HIDDEN, EMBED);
        ar_silu_mul<<<(MROWS * HIDDEN + 255) / 256, 256>>>(pu, pqkv, MROWS * HIDDEN);
        launch_gemm(pu, w2_l, nullptr, h, h, MROWS, EMBED, HIDDEN);
    }
}

// round 2
// speedup vs baseline: 2.2971x; 2.2971x over previous
#include <cuda_runtime.h>
#include <math.h>
#include <stdint.h>

#define EMBED   1024
#define HEADS   16
#define HD      64
#define NB      12
#define SEQ     257
#define BATCH   32
#define MROWS   (BATCH*SEQ)      // 8224
#define HIDDEN  2816

// ---------------- scratch (device globals; no allocations allowed) ----------
__device__ float g_a[MROWS*EMBED];        // normalized activations
__device__ float g_qkv[MROWS*3*EMBED];    // qkv / reused as w3-output
__device__ float g_o[MROWS*EMBED];        // attention output / cond temp
__device__ float g_u[MROWS*HIDDEN];       // w1 output -> fused silu*gate
__device__ float g_fc[SEQ*32*2];          // rope cos/sin table

// ---------------- reductions ------------------------------------------------
__device__ __forceinline__ float block_sum(float v, float* red) {
    int tid = threadIdx.x;
    #pragma unroll
    for (int o = 16; o > 0; o >>= 1) v += __shfl_xor_sync(0xffffffffu, v, o);
    if ((tid & 31) == 0) red[tid >> 5] = v;
    __syncthreads();
    if (tid == 0) {
        float s = red[0];
        int nw = blockDim.x >> 5;
        for (int i = 1; i < nw; i++) s += red[i];
        red[0] = s;
    }
    __syncthreads();
    float r = red[0];
    __syncthreads();
    return r;
}

__device__ __forceinline__ float block_max(float v, float* red) {
    int tid = threadIdx.x;
    #pragma unroll
    for (int o = 16; o > 0; o >>= 1) v = fmaxf(v, __shfl_xor_sync(0xffffffffu, v, o));
    if ((tid & 31) == 0) red[tid >> 5] = v;
    __syncthreads();
    if (tid == 0) {
        float s = red[0];
        int nw = blockDim.x >> 5;
        for (int i = 1; i < nw; i++) s = fmaxf(s, red[i]);
        red[0] = s;
    }
    __syncthreads();
    float r = red[0];
    __syncthreads();
    return r;
}

// ---------------- tf32 helpers ----------------------------------------------
__device__ __forceinline__ uint32_t f2tf(float x) {
    uint32_t r;
    asm("cvt.rna.tf32.f32 %0, %1;" : "=r"(r) : "f"(x));
    return r;
}

__device__ __forceinline__ void mma_tf32(float c[4], const uint32_t a[4],
                                         const uint32_t b[2]) {
    asm volatile(
        "mma.sync.aligned.m16n8k8.row.col.f32.tf32.tf32.f32 "
        "{%0,%1,%2,%3}, {%4,%5,%6,%7}, {%8,%9}, {%0,%1,%2,%3};"
        : "+f"(c[0]), "+f"(c[1]), "+f"(c[2]), "+f"(c[3])
        : "r"(a[0]), "r"(a[1]), "r"(a[2]), "r"(a[3]), "r"(b[0]), "r"(b[1]));
}

// ---------------- TF32 tensor-core GEMM -------------------------------------
// C[M,N] = A[M,K] @ B[K,N] (+bias[N]) (+res[M,N])
// Block tile 128x128, BK=16, 256 threads (8 warps, 4(M) x 2(N)), warp 32x64.
// N % 128 == 0 and K % 16 == 0 are assumed (true for all call sites).
__global__ __launch_bounds__(256) void ar_gemm_tf32(
    const float* __restrict__ A, const float* __restrict__ B,
    const float* __restrict__ bias, const float* __restrict__ res,
    float* __restrict__ C, int M, int N, int K)
{
    __shared__ uint32_t As[16][136];   // k-major, pad 136 -> conflict-free frag reads
    __shared__ uint32_t Bs[16][136];

    int tid = threadIdx.x, lane = tid & 31, warp = tid >> 5;
    int wm = warp >> 1, wn = warp & 1;              // 4x2 warp grid
    int bm = blockIdx.y * 128, bn = blockIdx.x * 128;

    float acc[2][8][4];
    #pragma unroll
    for (int i = 0; i < 2; i++)
        #pragma unroll
        for (int j = 0; j < 8; j++)
            #pragma unroll
            for (int t = 0; t < 4; t++) acc[i][j][t] = 0.f;

    // global staging indices
    int arow = tid >> 2, acol = (tid & 3) << 2;     // A: rows arow, arow+64
    int brow = tid >> 5, bcol = (tid & 31) << 2;    // B: rows brow, brow+8

    const float* Ap = A + (size_t)(bm + arow) * K + acol;
    const float* Bp = B + (size_t)brow * N + bn + bcol;

    int mfrag = wm * 32 + (lane >> 2);
    int nfrag = wn * 64 + (lane >> 2);
    int kfrag = lane & 3;

    for (int k0 = 0; k0 < K; k0 += 16) {
        #pragma unroll
        for (int i = 0; i < 2; i++) {
            int r = arow + i * 64;
            float4 v = make_float4(0.f, 0.f, 0.f, 0.f);
            if (bm + r < M) v = *(const float4*)(Ap + (size_t)i * 64 * K);
            As[acol + 0][r] = f2tf(v.x);
            As[acol + 1][r] = f2tf(v.y);
            As[acol + 2][r] = f2tf(v.z);
            As[acol + 3][r] = f2tf(v.w);
        }
        #pragma unroll
        for (int i = 0; i < 2; i++) {
            float4 v = *(const float4*)(Bp + (size_t)(i * 8) * N);
            uint32_t* d = &Bs[brow + i * 8][bcol];
            d[0] = f2tf(v.x); d[1] = f2tf(v.y); d[2] = f2tf(v.z); d[3] = f2tf(v.w);
        }
        __syncthreads();

        #pragma unroll
        for (int kk = 0; kk < 16; kk += 8) {
            int kb = kk + kfrag;
            uint32_t af[2][4];
            #pragma unroll
            for (int t = 0; t < 2; t++) {
                int m0 = mfrag + t * 16;
                af[t][0] = As[kb][m0];
                af[t][1] = As[kb][m0 + 8];
                af[t][2] = As[kb + 4][m0];
                af[t][3] = As[kb + 4][m0 + 8];
            }
            uint32_t bf[8][2];
            #pragma unroll
            for (int t = 0; t < 8; t++) {
                int n0 = nfrag + t * 8;
                bf[t][0] = Bs[kb][n0];
                bf[t][1] = Bs[kb + 4][n0];
            }
            #pragma unroll
            for (int mt = 0; mt < 2; mt++)
                #pragma unroll
                for (int nt = 0; nt < 8; nt++)
                    mma_tf32(acc[mt][nt], af[mt], bf[nt]);
        }
        __syncthreads();
        Ap += 16;
        Bp += (size_t)16 * N;
    }

    // epilogue
    #pragma unroll
    for (int mt = 0; mt < 2; mt++) {
        int rbase = bm + wm * 32 + mt * 16 + (lane >> 2);
        #pragma unroll
        for (int half = 0; half < 2; half++) {
            int r = rbase + half * 8;
            if (r >= M) continue;
            #pragma unroll
            for (int nt = 0; nt < 8; nt++) {
                int cl = bn + wn * 64 + nt * 8 + 2 * (lane & 3);
                float2 v;
                v.x = acc[mt][nt][half * 2 + 0];
                v.y = acc[mt][nt][half * 2 + 1];
                if (bias) { v.x += bias[cl]; v.y += bias[cl + 1]; }
                if (res) {
                    float2 rr = *(const float2*)(res + (size_t)r * N + cl);
                    v.x += rr.x; v.y += rr.y;
                }
                *(float2*)(C + (size_t)r * N + cl) = v;
            }
        }
    }
}

// ---------------- rope frequency table --------------------------------------
__global__ void ar_freqs(float* __restrict__ fc) {
    int t = blockIdx.x * blockDim.x + threadIdx.x;
    if (t >= SEQ * 32) return;
    int p = t >> 5, j = t & 31;
    float c = 0.f, s = 0.f;
    if (p > 0) {                       // cls token (p==0) keeps cos=sin=0 (ref!)
        int pp = p - 1, yy = pp >> 4, xx = pp & 15;
        int i = j & 15;
        float fr = powf(10000.0f, -(float)i * (1.0f / 16.0f));
        float tt = (j < 16) ? (float)yy : (float)xx;
        float ang = tt * fr;
        c = cosf(ang); s = sinf(ang);
    }
    fc[2 * t] = c;
    fc[2 * t + 1] = s;
}

// ---------------- assemble (cond | patch) + pos + LayerNorm ------------------
__global__ __launch_bounds__(256) void ar_assemble_ln(
    const float* __restrict__ patch, const float* __restrict__ condr,
    const float* __restrict__ pos, const float* __restrict__ g,
    const float* __restrict__ bta, float* __restrict__ h)
{
    __shared__ float buf[EMBED];
    __shared__ float red[8];
    int m = blockIdx.x, tid = threadIdx.x;
    int b = m / SEQ, s = m % SEQ;
    const float* src = (s == 0) ? (condr + (size_t)b * EMBED)
                                : (patch + ((size_t)(b * 256 + s - 1)) * EMBED);
    float lsum = 0.f;
    for (int d = tid; d < EMBED; d += 256) {
        float v = src[d] + pos[(size_t)s * EMBED + d];
        buf[d] = v; lsum += v;
    }
    float mean = block_sum(lsum, red) * (1.f / EMBED);
    float ls2 = 0.f;
    for (int d = tid; d < EMBED; d += 256) {
        float dv = buf[d] - mean; ls2 += dv * dv;
    }
    float var = block_sum(ls2, red) * (1.f / EMBED);
    float rinv = rsqrtf(var + 1e-6f);
    for (int d = tid; d < EMBED; d += 256)
        h[(size_t)m * EMBED + d] = (buf[d] - mean) * rinv * g[d] + bta[d];
}

// ---------------- RMSNorm ---------------------------------------------------
__global__ __launch_bounds__(256) void ar_rmsnorm(
    const float* __restrict__ x, const float* __restrict__ w, float* __restrict__ out)
{
    __shared__ float buf[EMBED];
    __shared__ float red[8];
    int m = blockIdx.x, tid = threadIdx.x;
    const float* xr = x + (size_t)m * EMBED;
    float ss = 0.f;
    for (int d = tid; d < EMBED; d += 256) {
        float v = xr[d]; buf[d] = v; ss += v * v;
    }
    ss = block_sum(ss, red);
    float r = rsqrtf(ss * (1.f / EMBED) + 1e-5f);
    for (int d = tid; d < EMBED; d += 256)
        out[(size_t)m * EMBED + d] = buf[d] * r * w[d];
}

// ---------------- rope (in-place on q and k halves of qkv) -------------------
__global__ void ar_rope(float* __restrict__ qkv, const float* __restrict__ fc) {
    int t = blockIdx.x * blockDim.x + threadIdx.x;
    if (t >= MROWS * 512) return;
    int m = t >> 9, r = t & 511;
    int hh = r >> 5, j = r & 31;
    int s = m % SEQ;
    float c  = fc[(s * 32 + j) * 2];
    float sn = fc[(s * 32 + j) * 2 + 1];
    float* q = qkv + (size_t)m * (3 * EMBED) + hh * HD + 2 * j;
    float x0 = q[0], x1 = q[1];
    q[0] = x0 * c - x1 * sn;
    q[1] = x1 * c + x0 * sn;
    float* k = q + EMBED;
    x0 = k[0]; x1 = k[1];
    k[0] = x0 * c - x1 * sn;
    k[1] = x1 * c + x0 * sn;
}

// ---------------- attention: rows 0..255, whole K/V in smem -----------------
__device__ __forceinline__ void ar_attn_row(
    int qrow, int b, int h, const float* __restrict__ qkv,
    const float* __restrict__ Ks, const float* __restrict__ Vs,
    float* __restrict__ o)
{
    const float4* qp = (const float4*)(qkv + ((size_t)(b * SEQ + qrow)) * (3 * EMBED) + h * HD);
    float4 qv[16];
    #pragma unroll
    for (int i = 0; i < 16; i++) qv[i] = qp[i];
    float acc[64];
    #pragma unroll
    for (int d = 0; d < 64; d++) acc[d] = 0.f;
    float mx = -1e30f, l = 0.f;
    for (int j = 0; j <= qrow; j++) {
        const float4* kr = (const float4*)(Ks + j * 64);
        float s0 = 0.f, s1 = 0.f, s2 = 0.f, s3 = 0.f;
        #pragma unroll
        for (int i = 0; i < 16; i++) {
            float4 kk = kr[i];
            s0 = fmaf(qv[i].x, kk.x, s0);
            s1 = fmaf(qv[i].y, kk.y, s1);
            s2 = fmaf(qv[i].z, kk.z, s2);
            s3 = fmaf(qv[i].w, kk.w, s3);
        }
        float s = ((s0 + s1) + (s2 + s3)) * 0.125f;
        float nm = fmaxf(mx, s);
        float corr = __expf(mx - nm);
        float p = __expf(s - nm);
        l = l * corr + p;
        const float4* vr = (const float4*)(Vs + j * 64);
        #pragma unroll
        for (int i = 0; i < 16; i++) {
            float4 vv = vr[i];
            acc[4*i+0] = fmaf(acc[4*i+0], corr, p * vv.x);
            acc[4*i+1] = fmaf(acc[4*i+1], corr, p * vv.y);
            acc[4*i+2] = fmaf(acc[4*i+2], corr, p * vv.z);
            acc[4*i+3] = fmaf(acc[4*i+3], corr, p * vv.w);
        }
        mx = nm;
    }
    float inv = 1.f / l;
    float* op = o + ((size_t)(b * SEQ + qrow)) * EMBED + h * HD;
    #pragma unroll
    for (int d = 0; d < 64; d++) op[d] = acc[d] * inv;
}

__global__ __launch_bounds__(128) void ar_attn(const float* __restrict__ qkv,
                                               float* __restrict__ o)
{
    extern __shared__ float sm[];
    float* Ks = sm;
    float* Vs = sm + SEQ * 64;
    int h = blockIdx.x, b = blockIdx.y, tid = threadIdx.x;
    const float* base = qkv + (size_t)b * SEQ * (3 * EMBED) + EMBED + h * HD;
    for (int idx = tid; idx < SEQ * 16; idx += 128) {
        int s = idx >> 4, c = idx & 15;
        *(float4*)(Ks + s * 64 + c * 4) = *(const float4*)(base + (size_t)s * (3 * EMBED) + c * 4);
        *(float4*)(Vs + s * 64 + c * 4) = *(const float4*)(base + EMBED + (size_t)s * (3 * EMBED) + c * 4);
    }
    __syncthreads();
    // triangle-balanced pairing: each thread gets rows t and 255-t -> 257 iters
    ar_attn_row(tid, b, h, qkv, Ks, Vs, o);
    ar_attn_row(255 - tid, b, h, qkv, Ks, Vs, o);
}

// ---------------- attention row 256 (longest row, j-parallel) ---------------
__global__ __launch_bounds__(256) void ar_attn_last(const float* __restrict__ qkv,
                                                    float* __restrict__ o)
{
    __shared__ float qs[64];
    __shared__ float sc[SEQ];
    __shared__ float red[8];
    __shared__ float part[4][64];
    int h = blockIdx.x, b = blockIdx.y, tid = threadIdx.x;
    const float* qrow = qkv + ((size_t)(b * SEQ + 256)) * (3 * EMBED) + h * HD;
    if (tid < 64) qs[tid] = qrow[tid];
    __syncthreads();
    const float* kbase = qkv + (size_t)b * SEQ * (3 * EMBED) + EMBED + (size_t)h * HD;
    float lm = -1e30f;
    for (int j = tid; j < SEQ; j += 256) {
        const float* kr = kbase + (size_t)j * (3 * EMBED);
        float s = 0.f;
        #pragma unroll
        for (int d = 0; d < 64; d++) s = fmaf(qs[d], kr[d], s);
        s *= 0.125f;
        sc[j] = s;
        lm = fmaxf(lm, s);
    }
    float M = block_max(lm, red);
    float ls = 0.f;
    for (int j = tid; j < SEQ; j += 256) {
        float p = __expf(sc[j] - M);
        sc[j] = p;
        ls += p;
    }
    float L = block_sum(ls, red);
    int d = tid & 63, c = tid >> 6;
    const float* vbase = kbase + EMBED;
    float a = 0.f;
    for (int j = c; j < SEQ; j += 4)
        a = fmaf(sc[j], vbase[(size_t)j * (3 * EMBED) + d], a);
    part[c][d] = a;
    __syncthreads();
    if (tid < 64) {
        float s = part[0][tid] + part[1][tid] + part[2][tid] + part[3][tid];
        o[((size_t)(b * SEQ + 256)) * EMBED + h * HD + tid] = s / L;
    }
}

// ---------------- fused silu(u) * v -----------------------------------------
__global__ void ar_silu_mul(float* __restrict__ u, const float* __restrict__ v, int n) {
    int i = blockIdx.x * blockDim.x + threadIdx.x;
    if (i < n) {
        float uu = u[i];
        float s = uu / (1.f + __expf(-uu));
        u[i] = s * v[i];
    }
}

// ---------------- host orchestration ----------------------------------------
static inline void launch_gemm(const float* A, const float* B, const float* bias,
                               const float* res, float* C, int M, int N, int K) {
    dim3 grid((N + 127) / 128, (M + 127) / 128);
    ar_gemm_tf32<<<grid, 256>>>(A, B, bias, res, C, M, N, K);
}

extern "C" void kernel_launch(void* const* d_in, const int* in_sizes, int n_in,
                              void* d_out, int out_size)
{
    const float* x       = (const float*)d_in[0];
    const float* cond    = (const float*)d_in[1];
    const float* patch_w = (const float*)d_in[2];
    const float* patch_b = (const float*)d_in[3];
    const float* ln_g    = (const float*)d_in[4];
    const float* ln_b    = (const float*)d_in[5];
    const float* pos     = (const float*)d_in[6];
    const float* cond_w  = (const float*)d_in[7];
    const float* cond_b  = (const float*)d_in[8];
    const float* wqkv    = (const float*)d_in[9];
    const float* wo      = (const float*)d_in[10];
    const float* w1      = (const float*)d_in[11];
    const float* w2      = (const float*)d_in[12];
    const float* w3      = (const float*)d_in[13];
    const float* anw     = (const float*)d_in[14];
    const float* fnw     = (const float*)d_in[15];
    float* h = (float*)d_out;

    float *pa, *pqkv, *po, *pu, *pfc;
    cudaGetSymbolAddress((void**)&pa,   g_a);
    cudaGetSymbolAddress((void**)&pqkv, g_qkv);
    cudaGetSymbolAddress((void**)&po,   g_o);
    cudaGetSymbolAddress((void**)&pu,   g_u);
    cudaGetSymbolAddress((void**)&pfc,  g_fc);

    cudaFuncSetAttribute(ar_attn, cudaFuncAttributeMaxDynamicSharedMemorySize,
                         SEQ * 64 * 2 * (int)sizeof(float));

    // rope table
    ar_freqs<<<(SEQ * 32 + 255) / 256, 256>>>(pfc);
    // patch embed (8192 x 768 @ 768 x 1024) -> g_a ; cond embed -> g_o
    launch_gemm(x, patch_w, patch_b, nullptr, pa, BATCH * 256, EMBED, 768);
    launch_gemm(cond, cond_w, cond_b, nullptr, po, BATCH, EMBED, EMBED);
    // assemble + pos + layernorm -> h (d_out)
    ar_assemble_ln<<<MROWS, 256>>>(pa, po, pos, ln_g, ln_b, h);

    for (int l = 0; l < NB; l++) {
        const float* wqkv_l = wqkv + (size_t)l * EMBED * (3 * EMBED);
        const float* wo_l   = wo   + (size_t)l * EMBED * EMBED;
        const float* w1_l   = w1   + (size_t)l * EMBED * HIDDEN;
        const float* w2_l   = w2   + (size_t)l * HIDDEN * EMBED;
        const float* w3_l   = w3   + (size_t)l * EMBED * HIDDEN;

        ar_rmsnorm<<<MROWS, 256>>>(h, anw + (size_t)l * EMBED, pa);
        launch_gemm(pa, wqkv_l, nullptr, nullptr, pqkv, MROWS, 3 * EMBED, EMBED);
        ar_rope<<<(MROWS * 512 + 255) / 256, 256>>>(pqkv, pfc);
        ar_attn<<<dim3(HEADS, BATCH), 128, SEQ * 64 * 2 * (int)sizeof(float)>>>(pqkv, po);
        ar_attn_last<<<dim3(HEADS, BATCH), 256>>>(pqkv, po);
        launch_gemm(po, wo_l, nullptr, h, h, MROWS, EMBED, EMBED);

        ar_rmsnorm<<<MROWS, 256>>>(h, fnw + (size_t)l * EMBED, pa);
        launch_gemm(pa, w1_l, nullptr, nullptr, pu, MROWS, HIDDEN, EMBED);
        launch_gemm(pa, w3_l, nullptr, nullptr, pqkv, MROWS, HIDDEN, EMBED);
        ar_silu_mul<<<(MROWS * HIDDEN + 255) / 256, 256>>>(pu, pqkv, MROWS * HIDDEN);
        launch_gemm(pu, w2_l, nullptr, h, h, MROWS, EMBED, HIDDEN);
    }
}

// round 5
// speedup vs baseline: 3.2611x; 1.4197x over previous
#include <cuda_runtime.h>
#include <math.h>
#include <stdint.h>

#define EMBED   1024
#define HEADS   16
#define HD      64
#define NB      12
#define SEQ     257
#define BATCH   32
#define MROWS   (BATCH*SEQ)      // 8224
#define HIDDEN  2816

// ---------------- scratch (device globals; no allocations allowed) ----------
__device__ __align__(256) float g_a[MROWS*EMBED];        // normalized activations (tf32-rounded)
__device__ __align__(256) float g_qkv[MROWS*3*EMBED];    // qkv / reused as w3-output
__device__ __align__(256) float g_o[MROWS*EMBED];        // attention output (tf32-rounded)
__device__ __align__(256) float g_u[MROWS*HIDDEN];       // silu(u)*v (tf32-rounded)
__device__ __align__(256) float g_fc[SEQ*32*2];          // rope cos/sin table
__device__ __align__(256) float g_xr[8192*768];          // tf32-rounded x
__device__ __align__(256) float g_cr[32*1024];           // tf32-rounded cond

// tf32-rounded weights (same layout as inputs, no transpose), one arena
#define OFF_QKV   ((size_t)0)
#define OFF_WO    (OFF_QKV + (size_t)NB*1024*3072)
#define OFF_W1    (OFF_WO  + (size_t)NB*1024*1024)
#define OFF_W3    (OFF_W1  + (size_t)NB*1024*HIDDEN)
#define OFF_W2    (OFF_W3  + (size_t)NB*1024*HIDDEN)
#define OFF_PATCH (OFF_W2  + (size_t)NB*HIDDEN*1024)
#define OFF_COND  (OFF_PATCH + (size_t)768*1024)
#define WT_TOTAL  (OFF_COND + (size_t)1024*1024)
__device__ __align__(256) float g_wt[WT_TOTAL];

// ---------------- helpers ----------------------------------------------------
__device__ __forceinline__ uint32_t smem_u32(const void* p) {
    uint32_t a;
    asm("{ .reg .u64 t; cvta.to.shared.u64 t, %1; cvt.u32.u64 %0, t; }" : "=r"(a) : "l"(p));
    return a;
}
__device__ __forceinline__ uint32_t f2tf(float x) {
    uint32_t r; asm("cvt.rna.tf32.f32 %0, %1;" : "=r"(r) : "f"(x)); return r;
}
__device__ __forceinline__ float rndf(float x) { return __uint_as_float(f2tf(x)); }

__device__ __forceinline__ void mma_tf32(float c[4], const uint32_t a[4],
                                         const uint32_t b[2]) {
    asm volatile(
        "mma.sync.aligned.m16n8k8.row.col.f32.tf32.tf32.f32 "
        "{%0,%1,%2,%3}, {%4,%5,%6,%7}, {%8,%9}, {%0,%1,%2,%3};"
        : "+f"(c[0]), "+f"(c[1]), "+f"(c[2]), "+f"(c[3])
        : "r"(a[0]), "r"(a[1]), "r"(a[2]), "r"(a[3]), "r"(b[0]), "r"(b[1]));
}

__device__ __forceinline__ void cp16(uint32_t dst, const void* src, int sz) {
    asm volatile("cp.async.cg.shared.global [%0], [%1], 16, %2;"
        :: "r"(dst), "l"(src), "r"(sz) : "memory");
}

// ---------------- pipelined TF32 tensor-core GEMM ----------------------------
// C[M,N] = A[M,K] @ B[K,N] (+bias) (+res). A,B pre-rounded to tf32 values.
// CTA tile 128x128, BK=32, double-buffered cp.async. 8 warps (4m x 2n), warp 32x64.
// A staged [m][k] stride 36 (conflict-free frags); B staged [k][n] stride 136.
#define A_ST   36
#define B_ST   136
#define A_FL   (128*A_ST)        // 4608 floats per stage
#define B_FL   (32*B_ST)         // 4352 floats per stage
#define G_SMEM ((2*(A_FL+B_FL))*4)   // 71680 bytes

__global__ __launch_bounds__(256) void ar_gemm_tf32(
    const float* __restrict__ A, const float* __restrict__ B,
    const float* __restrict__ bias, const float* __restrict__ res,
    float* __restrict__ C, int M, int N, int K)
{
    extern __shared__ float sm[];
    float* As = sm;                    // [2][128][36]
    float* Bs = sm + 2 * A_FL;         // [2][32][136]
    uint32_t as_u = smem_u32(As), bs_u = smem_u32(Bs);

    int tid = threadIdx.x, lane = tid & 31, warp = tid >> 5;
    int wm = warp >> 1, wn = warp & 1;
    int bm = blockIdx.y * 128, bn = blockIdx.x * 128;
    int g = lane >> 2, tg = lane & 3;

    float acc[2][8][4];
    #pragma unroll
    for (int i = 0; i < 2; i++)
        #pragma unroll
        for (int j = 0; j < 8; j++)
            #pragma unroll
            for (int t = 0; t < 4; t++) acc[i][j][t] = 0.f;

    const int NC = K >> 5;

    auto load_chunk = [&](int cidx) {
        int s = cidx & 1, k0 = cidx << 5;
        #pragma unroll
        for (int i = 0; i < 4; i++) {          // A: 1024 x 16B
            int idx = tid + (i << 8);
            int r = idx >> 3, cc = idx & 7;
            uint32_t dst = as_u + (uint32_t)(s * A_FL + r * A_ST + cc * 4) * 4u;
            int gm = bm + r;
            bool v = (gm < M);
            const float* src = A + (size_t)(v ? gm : 0) * K + k0 + cc * 4;
            cp16(dst, src, v ? 16 : 0);
        }
        #pragma unroll
        for (int i = 0; i < 4; i++) {          // B: 1024 x 16B
            int idx = tid + (i << 8);
            int r = idx >> 5, cc = idx & 31;
            uint32_t dst = bs_u + (uint32_t)(s * B_FL + r * B_ST + cc * 4) * 4u;
            const float* src = B + (size_t)(k0 + r) * N + bn + cc * 4;
            cp16(dst, src, 16);
        }
    };

    auto compute = [&](int s) {
        const float* Ab = As + s * A_FL;
        const float* Bb = Bs + s * B_FL;
        int m0 = wm * 32 + g;
        int n0 = wn * 64 + g;
        #pragma unroll
        for (int kb = 0; kb < 32; kb += 8) {
            uint32_t af[2][4];
            #pragma unroll
            for (int t = 0; t < 2; t++) {
                const float* ar0 = Ab + (m0 + t * 16) * A_ST + kb + tg;
                af[t][0] = __float_as_uint(ar0[0]);
                af[t][1] = __float_as_uint(ar0[8 * A_ST]);
                af[t][2] = __float_as_uint(ar0[4]);
                af[t][3] = __float_as_uint(ar0[8 * A_ST + 4]);
            }
            uint32_t bf[8][2];
            #pragma unroll
            for (int t = 0; t < 8; t++) {
                const float* br = Bb + (kb + tg) * B_ST + n0 + t * 8;
                bf[t][0] = __float_as_uint(br[0]);
                bf[t][1] = __float_as_uint(br[4 * B_ST]);
            }
            #pragma unroll
            for (int mt = 0; mt < 2; mt++)
                #pragma unroll
                for (int nt = 0; nt < 8; nt++)
                    mma_tf32(acc[mt][nt], af[mt], bf[nt]);
        }
    };

    load_chunk(0);
    asm volatile("cp.async.commit_group;" ::: "memory");
    for (int c = 0; c < NC; c++) {
        if (c + 1 < NC) {
            load_chunk(c + 1);
            asm volatile("cp.async.commit_group;" ::: "memory");
            asm volatile("cp.async.wait_group 1;" ::: "memory");
        } else {
            asm volatile("cp.async.wait_group 0;" ::: "memory");
        }
        __syncthreads();
        compute(c & 1);
        __syncthreads();
    }

    // epilogue (same fragment mapping as validated R2 kernel)
    #pragma unroll
    for (int mt = 0; mt < 2; mt++) {
        int rbase = bm + wm * 32 + mt * 16 + g;
        #pragma unroll
        for (int half = 0; half < 2; half++) {
            int r = rbase + half * 8;
            if (r >= M) continue;
            #pragma unroll
            for (int nt = 0; nt < 8; nt++) {
                int cl = bn + wn * 64 + nt * 8 + 2 * tg;
                float2 v;
                v.x = acc[mt][nt][half * 2 + 0];
                v.y = acc[mt][nt][half * 2 + 1];
                if (bias) { v.x += bias[cl]; v.y += bias[cl + 1]; }
                if (res) {
                    float2 rr = *(const float2*)(res + (size_t)r * N + cl);
                    v.x += rr.x; v.y += rr.y;
                }
                *(float2*)(C + (size_t)r * N + cl) = v;
            }
        }
    }
}

// ---------------- vectorized tf32 round-copy ---------------------------------
__global__ void ar_round4(const float* __restrict__ in, float* __restrict__ out,
                          size_t n4) {
    size_t i = (size_t)blockIdx.x * blockDim.x + threadIdx.x;
    if (i < n4) {
        float4 v = ((const float4*)in)[i];
        v.x = rndf(v.x); v.y = rndf(v.y); v.z = rndf(v.z); v.w = rndf(v.w);
        ((float4*)out)[i] = v;
    }
}

// ---------------- reductions ------------------------------------------------
__device__ __forceinline__ float block_sum(float v, float* red) {
    int tid = threadIdx.x;
    #pragma unroll
    for (int o = 16; o > 0; o >>= 1) v += __shfl_xor_sync(0xffffffffu, v, o);
    if ((tid & 31) == 0) red[tid >> 5] = v;
    __syncthreads();
    if (tid == 0) {
        float s = red[0];
        int nw = blockDim.x >> 5;
        for (int i = 1; i < nw; i++) s += red[i];
        red[0] = s;
    }
    __syncthreads();
    float r = red[0];
    __syncthreads();
    return r;
}

__device__ __forceinline__ float block_max(float v, float* red) {
    int tid = threadIdx.x;
    #pragma unroll
    for (int o = 16; o > 0; o >>= 1) v = fmaxf(v, __shfl_xor_sync(0xffffffffu, v, o));
    if ((tid & 31) == 0) red[tid >> 5] = v;
    __syncthreads();
    if (tid == 0) {
        float s = red[0];
        int nw = blockDim.x >> 5;
        for (int i = 1; i < nw; i++) s = fmaxf(s, red[i]);
        red[0] = s;
    }
    __syncthreads();
    float r = red[0];
    __syncthreads();
    return r;
}

// ---------------- rope frequency table --------------------------------------
__global__ void ar_freqs(float* __restrict__ fc) {
    int t = blockIdx.x * blockDim.x + threadIdx.x;
    if (t >= SEQ * 32) return;
    int p = t >> 5, j = t & 31;
    float c = 0.f, s = 0.f;
    if (p > 0) {                       // cls token keeps cos=sin=0 (ref!)
        int pp = p - 1, yy = pp >> 4, xx = pp & 15;
        int i = j & 15;
        float fr = powf(10000.0f, -(float)i * (1.0f / 16.0f));
        float tt = (j < 16) ? (float)yy : (float)xx;
        float ang = tt * fr;
        c = cosf(ang); s = sinf(ang);
    }
    fc[2 * t] = c;
    fc[2 * t + 1] = s;
}

// ---------------- assemble (cond | patch) + pos + LayerNorm ------------------
__global__ __launch_bounds__(256) void ar_assemble_ln(
    const float* __restrict__ patch, const float* __restrict__ condr,
    const float* __restrict__ pos, const float* __restrict__ g,
    const float* __restrict__ bta, float* __restrict__ h)
{
    __shared__ float buf[EMBED];
    __shared__ float red[8];
    int m = blockIdx.x, tid = threadIdx.x;
    int b = m / SEQ, s = m % SEQ;
    const float* src = (s == 0) ? (condr + (size_t)b * EMBED)
                                : (patch + ((size_t)(b * 256 + s - 1)) * EMBED);
    float lsum = 0.f;
    for (int d = tid; d < EMBED; d += 256) {
        float v = src[d] + pos[(size_t)s * EMBED + d];
        buf[d] = v; lsum += v;
    }
    float mean = block_sum(lsum, red) * (1.f / EMBED);
    float ls2 = 0.f;
    for (int d = tid; d < EMBED; d += 256) {
        float dv = buf[d] - mean; ls2 += dv * dv;
    }
    float var = block_sum(ls2, red) * (1.f / EMBED);
    float rinv = rsqrtf(var + 1e-6f);
    for (int d = tid; d < EMBED; d += 256)
        h[(size_t)m * EMBED + d] = (buf[d] - mean) * rinv * g[d] + bta[d];
}

// ---------------- RMSNorm (tf32-rounded output: feeds GEMM A) ----------------
__global__ __launch_bounds__(256) void ar_rmsnorm(
    const float* __restrict__ x, const float* __restrict__ w, float* __restrict__ out)
{
    __shared__ float buf[EMBED];
    __shared__ float red[8];
    int m = blockIdx.x, tid = threadIdx.x;
    const float* xr = x + (size_t)m * EMBED;
    float ss = 0.f;
    for (int d = tid; d < EMBED; d += 256) {
        float v = xr[d]; buf[d] = v; ss += v * v;
    }
    ss = block_sum(ss, red);
    float r = rsqrtf(ss * (1.f / EMBED) + 1e-5f);
    for (int d = tid; d < EMBED; d += 256)
        out[(size_t)m * EMBED + d] = rndf(buf[d] * r * w[d]);
}

// ---------------- rope (in-place on q and k halves of qkv) -------------------
__global__ void ar_rope(float* __restrict__ qkv, const float* __restrict__ fc) {
    int t = blockIdx.x * blockDim.x + threadIdx.x;
    if (t >= MROWS * 512) return;
    int m = t >> 9, r = t & 511;
    int hh = r >> 5, j = r & 31;
    int s = m % SEQ;
    float c  = fc[(s * 32 + j) * 2];
    float sn = fc[(s * 32 + j) * 2 + 1];
    float* q = qkv + (size_t)m * (3 * EMBED) + hh * HD + 2 * j;
    float x0 = q[0], x1 = q[1];
    q[0] = x0 * c - x1 * sn;
    q[1] = x1 * c + x0 * sn;
    float* k = q + EMBED;
    x0 = k[0]; x1 = k[1];
    k[0] = x0 * c - x1 * sn;
    k[1] = x1 * c + x0 * sn;
}

// ---------------- attention: rows 0..255, whole K/V in smem -----------------
__device__ __forceinline__ void ar_attn_row(
    int qrow, int b, int h, const float* __restrict__ qkv,
    const float* __restrict__ Ks, const float* __restrict__ Vs,
    float* __restrict__ o)
{
    const float4* qp = (const float4*)(qkv + ((size_t)(b * SEQ + qrow)) * (3 * EMBED) + h * HD);
    float4 qv[16];
    #pragma unroll
    for (int i = 0; i < 16; i++) qv[i] = qp[i];
    float acc[64];
    #pragma unroll
    for (int d = 0; d < 64; d++) acc[d] = 0.f;
    float mx = -1e30f, l = 0.f;
    for (int j = 0; j <= qrow; j++) {
        const float4* kr = (const float4*)(Ks + j * 64);
        float s0 = 0.f, s1 = 0.f, s2 = 0.f, s3 = 0.f;
        #pragma unroll
        for (int i = 0; i < 16; i++) {
            float4 kk = kr[i];
            s0 = fmaf(qv[i].x, kk.x, s0);
            s1 = fmaf(qv[i].y, kk.y, s1);
            s2 = fmaf(qv[i].z, kk.z, s2);
            s3 = fmaf(qv[i].w, kk.w, s3);
        }
        float s = ((s0 + s1) + (s2 + s3)) * 0.125f;
        float nm = fmaxf(mx, s);
        float corr = __expf(mx - nm);
        float p = __expf(s - nm);
        l = l * corr + p;
        const float4* vr = (const float4*)(Vs + j * 64);
        #pragma unroll
        for (int i = 0; i < 16; i++) {
            float4 vv = vr[i];
            acc[4*i+0] = fmaf(acc[4*i+0], corr, p * vv.x);
            acc[4*i+1] = fmaf(acc[4*i+1], corr, p * vv.y);
            acc[4*i+2] = fmaf(acc[4*i+2], corr, p * vv.z);
            acc[4*i+3] = fmaf(acc[4*i+3], corr, p * vv.w);
        }
        mx = nm;
    }
    float inv = 1.f / l;
    float* op = o + ((size_t)(b * SEQ + qrow)) * EMBED + h * HD;
    #pragma unroll
    for (int d = 0; d < 64; d++) op[d] = rndf(acc[d] * inv);
}

__global__ __launch_bounds__(128) void ar_attn(const float* __restrict__ qkv,
                                               float* __restrict__ o)
{
    extern __shared__ float smkv[];
    float* Ks = smkv;
    float* Vs = smkv + SEQ * 64;
    int h = blockIdx.x, b = blockIdx.y, tid = threadIdx.x;
    const float* base = qkv + (size_t)b * SEQ * (3 * EMBED) + EMBED + h * HD;
    for (int idx = tid; idx < SEQ * 16; idx += 128) {
        int s = idx >> 4, c = idx & 15;
        *(float4*)(Ks + s * 64 + c * 4) = *(const float4*)(base + (size_t)s * (3 * EMBED) + c * 4);
        *(float4*)(Vs + s * 64 + c * 4) = *(const float4*)(base + EMBED + (size_t)s * (3 * EMBED) + c * 4);
    }
    __syncthreads();
    ar_attn_row(tid, b, h, qkv, Ks, Vs, o);
    ar_attn_row(255 - tid, b, h, qkv, Ks, Vs, o);
}

// ---------------- attention row 256 (longest row, j-parallel) ---------------
__global__ __launch_bounds__(256) void ar_attn_last(const float* __restrict__ qkv,
                                                    float* __restrict__ o)
{
    __shared__ float qs[64];
    __shared__ float sc[SEQ];
    __shared__ float red[8];
    __shared__ float part[4][64];
    int h = blockIdx.x, b = blockIdx.y, tid = threadIdx.x;
    const float* qrow = qkv + ((size_t)(b * SEQ + 256)) * (3 * EMBED) + h * HD;
    if (tid < 64) qs[tid] = qrow[tid];
    __syncthreads();
    const float* kbase = qkv + (size_t)b * SEQ * (3 * EMBED) + EMBED + (size_t)h * HD;
    float lm = -1e30f;
    for (int j = tid; j < SEQ; j += 256) {
        const float* kr = kbase + (size_t)j * (3 * EMBED);
        float s = 0.f;
        #pragma unroll
        for (int d = 0; d < 64; d++) s = fmaf(qs[d], kr[d], s);
        s *= 0.125f;
        sc[j] = s;
        lm = fmaxf(lm, s);
    }
    float M = block_max(lm, red);
    float ls = 0.f;
    for (int j = tid; j < SEQ; j += 256) {
        float p = __expf(sc[j] - M);
        sc[j] = p;
        ls += p;
    }
    float L = block_sum(ls, red);
    int d = tid & 63, c = tid >> 6;
    const float* vbase = kbase + EMBED;
    float a = 0.f;
    for (int j = c; j < SEQ; j += 4)
        a = fmaf(sc[j], vbase[(size_t)j * (3 * EMBED) + d], a);
    part[c][d] = a;
    __syncthreads();
    if (tid < 64) {
        float s = part[0][tid] + part[1][tid] + part[2][tid] + part[3][tid];
        o[((size_t)(b * SEQ + 256)) * EMBED + h * HD + tid] = rndf(s / L);
    }
}

// ---------------- fused silu(u) * v (rounded: feeds GEMM A) -----------------
__global__ void ar_silu_mul(float* __restrict__ u, const float* __restrict__ v, int n) {
    int i = blockIdx.x * blockDim.x + threadIdx.x;
    if (i < n) {
        float uu = u[i];
        float s = uu / (1.f + __expf(-uu));
        u[i] = rndf(s * v[i]);
    }
}

// ---------------- host orchestration ----------------------------------------
static inline void launch_gemm(const float* A, const float* B, const float* bias,
                               const float* res, float* C, int M, int N, int K) {
    dim3 grid(N / 128, (M + 127) / 128);
    ar_gemm_tf32<<<grid, 256, G_SMEM>>>(A, B, bias, res, C, M, N, K);
}

static inline void launch_round(const float* in, float* out, size_t n) {
    size_t n4 = n / 4;
    ar_round4<<<(unsigned)((n4 + 255) / 256), 256>>>(in, out, n4);
}

extern "C" void kernel_launch(void* const* d_in, const int* in_sizes, int n_in,
                              void* d_out, int out_size)
{
    const float* x       = (const float*)d_in[0];
    const float* cond    = (const float*)d_in[1];
    const float* patch_w = (const float*)d_in[2];
    const float* patch_b = (const float*)d_in[3];
    const float* ln_g    = (const float*)d_in[4];
    const float* ln_b    = (const float*)d_in[5];
    const float* pos     = (const float*)d_in[6];
    const float* cond_w  = (const float*)d_in[7];
    const float* cond_b  = (const float*)d_in[8];
    const float* wqkv    = (const float*)d_in[9];
    const float* wo      = (const float*)d_in[10];
    const float* w1      = (const float*)d_in[11];
    const float* w2      = (const float*)d_in[12];
    const float* w3      = (const float*)d_in[13];
    const float* anw     = (const float*)d_in[14];
    const float* fnw     = (const float*)d_in[15];
    float* h = (float*)d_out;

    float *pa, *pqkv, *po, *pu, *pfc, *pxr, *pcr, *pwt;
    cudaGetSymbolAddress((void**)&pa,   g_a);
    cudaGetSymbolAddress((void**)&pqkv, g_qkv);
    cudaGetSymbolAddress((void**)&po,   g_o);
    cudaGetSymbolAddress((void**)&pu,   g_u);
    cudaGetSymbolAddress((void**)&pfc,  g_fc);
    cudaGetSymbolAddress((void**)&pxr,  g_xr);
    cudaGetSymbolAddress((void**)&pcr,  g_cr);
    cudaGetSymbolAddress((void**)&pwt,  g_wt);

    cudaFuncSetAttribute(ar_attn, cudaFuncAttributeMaxDynamicSharedMemorySize,
                         SEQ * 64 * 2 * (int)sizeof(float));
    cudaFuncSetAttribute(ar_gemm_tf32, cudaFuncAttributeMaxDynamicSharedMemorySize,
                         G_SMEM);

    float* qkvR   = pwt + OFF_QKV;
    float* woR    = pwt + OFF_WO;
    float* w1R    = pwt + OFF_W1;
    float* w3R    = pwt + OFF_W3;
    float* w2R    = pwt + OFF_W2;
    float* patchR = pwt + OFF_PATCH;
    float* condR  = pwt + OFF_COND;

    // tf32 round-copy all weights + A-side raw inputs (once per launch)
    launch_round(wqkv,    qkvR,   (size_t)NB * 1024 * 3072);
    launch_round(wo,      woR,    (size_t)NB * 1024 * 1024);
    launch_round(w1,      w1R,    (size_t)NB * 1024 * HIDDEN);
    launch_round(w3,      w3R,    (size_t)NB * 1024 * HIDDEN);
    launch_round(w2,      w2R,    (size_t)NB * HIDDEN * 1024);
    launch_round(patch_w, patchR, (size_t)768 * 1024);
    launch_round(cond_w,  condR,  (size_t)1024 * 1024);
    launch_round(x,       pxr,    (size_t)8192 * 768);
    launch_round(cond,    pcr,    (size_t)32 * 1024);

    // rope table
    ar_freqs<<<(SEQ * 32 + 255) / 256, 256>>>(pfc);
    // patch embed -> g_a ; cond embed -> g_o
    launch_gemm(pxr, patchR, patch_b, nullptr, pa, BATCH * 256, EMBED, 768);
    launch_gemm(pcr, condR, cond_b, nullptr, po, BATCH, EMBED, EMBED);
    // assemble + pos + layernorm -> h (d_out)
    ar_assemble_ln<<<MROWS, 256>>>(pa, po, pos, ln_g, ln_b, h);

    for (int l = 0; l < NB; l++) {
        float* qkv_l = qkvR + (size_t)l * 1024 * 3072;
        float* wo_l  = woR  + (size_t)l * 1024 * 1024;
        float* w1_l  = w1R  + (size_t)l * 1024 * HIDDEN;
        float* w3_l  = w3R  + (size_t)l * 1024 * HIDDEN;
        float* w2_l  = w2R  + (size_t)l * HIDDEN * 1024;

        ar_rmsnorm<<<MROWS, 256>>>(h, anw + (size_t)l * EMBED, pa);
        launch_gemm(pa, qkv_l, nullptr, nullptr, pqkv, MROWS, 3 * EMBED, EMBED);
        ar_rope<<<(MROWS * 512 + 255) / 256, 256>>>(pqkv, pfc);
        ar_attn<<<dim3(HEADS, BATCH), 128, SEQ * 64 * 2 * (int)sizeof(float)>>>(pqkv, po);
        ar_attn_last<<<dim3(HEADS, BATCH), 256>>>(pqkv, po);
        launch_gemm(po, wo_l, nullptr, h, h, MROWS, EMBED, EMBED);

        ar_rmsnorm<<<MROWS, 256>>>(h, fnw + (size_t)l * EMBED, pa);
        launch_gemm(pa, w1_l, nullptr, nullptr, pu, MROWS, HIDDEN, EMBED);
        launch_gemm(pa, w3_l, nullptr, nullptr, pqkv, MROWS, HIDDEN, EMBED);
        ar_silu_mul<<<(MROWS * HIDDEN + 255) / 256, 256>>>(pu, pqkv, MROWS * HIDDEN);
        launch_gemm(pu, w2_l, nullptr, h, h, MROWS, EMBED, HIDDEN);
    }
}